// round 15
// baseline (speedup 1.0000x reference)
#include <cuda_runtime.h>
#include <cuda_fp16.h>
#include <math.h>
#include <stdint.h>

#define N_NODES 100000
#define N_EDGES 1600000
#define NFEAT   512
#define NHID    128
#define NCLASS  40
#define H2S     48     // padded H2 row stride (halfs): 96B, sector-aligned

// ---------------- static scratch (no allocation allowed) ----------------
__device__ __half d_H1h[(size_t)N_NODES * NHID];   // features @ W1   (fp16)
__device__ __half d_X1h[(size_t)N_NODES * NHID];   // relu(agg1+b1)   (fp16)
__device__ __half d_H2h[(size_t)N_NODES * H2S];    // X1 @ W2         (fp16, padded)
__device__ int   d_deg[N_NODES];
__device__ int   d_cursor[N_NODES];
__device__ int   d_rowptr[N_NODES + 1];
__device__ int   d_blk[128];
__device__ int2  d_csr_sw[N_EDGES];               // {src, bits(weight)} packed
__device__ __half d_W1T16[(size_t)NHID * NFEAT];  // W1^T fp16, [n][k]

// ---------------- f32x2 helpers (packed dual-fp32 pipe) ----------------
__device__ __forceinline__ unsigned long long pk2(float x, float y) {
    unsigned long long r;
    asm("mov.b64 %0, {%1, %2};" : "=l"(r) : "f"(x), "f"(y));
    return r;
}
__device__ __forceinline__ void fma2(unsigned long long &d, unsigned long long a, unsigned long long b) {
    asm("fma.rn.f32x2 %0, %1, %2, %0;" : "+l"(d) : "l"(a), "l"(b));
}
__device__ __forceinline__ float2 upk(unsigned long long v) {
    float x, y;
    asm("mov.b64 {%0, %1}, %2;" : "=f"(x), "=f"(y) : "l"(v));
    return make_float2(x, y);
}

// ---------------- warp-mma helpers ----------------
__device__ __forceinline__ uint32_t smem_u32(const void* p) {
    uint32_t a;
    asm("{ .reg .u64 t; cvta.to.shared.u64 t, %1; cvt.u32.u64 %0, t; }" : "=r"(a) : "l"(p));
    return a;
}
__device__ __forceinline__ void ldsm4(uint32_t* r, uint32_t addr) {
    asm volatile("ldmatrix.sync.aligned.m8n8.x4.shared.b16 {%0,%1,%2,%3}, [%4];"
                 : "=r"(r[0]), "=r"(r[1]), "=r"(r[2]), "=r"(r[3]) : "r"(addr));
}
__device__ __forceinline__ void mma_f16(float* d, const uint32_t* a, const uint32_t* b) {
    asm volatile(
        "mma.sync.aligned.m16n8k16.row.col.f32.f16.f16.f32 "
        "{%0,%1,%2,%3}, {%4,%5,%6,%7}, {%8,%9}, {%0,%1,%2,%3};"
        : "+f"(d[0]), "+f"(d[1]), "+f"(d[2]), "+f"(d[3])
        : "r"(a[0]), "r"(a[1]), "r"(a[2]), "r"(a[3]), "r"(b[0]), "r"(b[1]));
}
__device__ __forceinline__ uint32_t lds_cvt(uint32_t addr) {
    float x, y;
    asm volatile("ld.shared.v2.f32 {%0,%1}, [%2];" : "=f"(x), "=f"(y) : "r"(addr));
    uint32_t r;
    asm("cvt.rn.f16x2.f32 %0, %1, %2;" : "=r"(r) : "f"(y), "f"(x));   // hi=y, lo=x
    return r;
}
__device__ __forceinline__ void cp_async16(uint32_t dst, const void* src) {
    asm volatile("cp.async.cg.shared.global [%0], [%1], 16;" :: "r"(dst), "l"(src));
}
__device__ __forceinline__ float2 h2f(uint32_t bits) {
    __half2 h = *reinterpret_cast<__half2*>(&bits);
    return __half22float2(h);
}

// ---------------- fused W1^T fp16 prep + degree zero ----------------
__global__ void k_prep(const float* __restrict__ W1) {
    int t = blockIdx.x * blockDim.x + threadIdx.x;
    if (t < NHID * (NFEAT / 8)) {
        int n  = t & (NHID - 1);
        int kb = t >> 7;
        __align__(16) __half h[8];
        #pragma unroll
        for (int j = 0; j < 8; j++)
            h[j] = __float2half_rn(W1[(size_t)(kb * 8 + j) * NHID + n]);
        *reinterpret_cast<uint4*>(d_W1T16 + (size_t)n * NFEAT + kb * 8) =
            *reinterpret_cast<uint4*>(h);
    }
    for (int i = t; i < N_NODES; i += gridDim.x * blockDim.x) d_deg[i] = 0;
}

__global__ void k_hist(const int* __restrict__ dst) {
    int e = blockIdx.x * blockDim.x + threadIdx.x;
    if (e < N_EDGES) atomicAdd(&d_deg[dst[e]], 1);
}

#define SCAN_CHUNK 1024
#define SCAN_BLOCKS ((N_NODES + SCAN_CHUNK - 1) / SCAN_CHUNK)   // 98

// shfl-based block scan (2 barriers)
__global__ void __launch_bounds__(SCAN_CHUNK) k_scan1() {
    __shared__ int wsum[32];
    int i = blockIdx.x * SCAN_CHUNK + threadIdx.x;
    int v = (i < N_NODES) ? d_deg[i] : 0;
    int lane = threadIdx.x & 31, w = threadIdx.x >> 5;
    int x = v;
    #pragma unroll
    for (int off = 1; off < 32; off <<= 1) {
        int y = __shfl_up_sync(0xffffffffu, x, off);
        if (lane >= off) x += y;
    }
    if (lane == 31) wsum[w] = x;
    __syncthreads();
    if (w == 0) {
        int s = wsum[lane];
        #pragma unroll
        for (int off = 1; off < 32; off <<= 1) {
            int y = __shfl_up_sync(0xffffffffu, s, off);
            if (lane >= off) s += y;
        }
        wsum[lane] = s;
    }
    __syncthreads();
    int incl = x + (w > 0 ? wsum[w - 1] : 0);
    if (i < N_NODES) d_rowptr[i] = incl - v;            // exclusive within block
    if (threadIdx.x == SCAN_CHUNK - 1) d_blk[blockIdx.x] = incl;
}

// fused scan2+scan3: per-block cross-block prefix + rowptr fixup + cursor init
__global__ void __launch_bounds__(SCAN_CHUNK) k_scan23() {
    __shared__ int spref;
    int b = blockIdx.x;
    if (threadIdx.x < 32) {
        int acc = 0;
        for (int i = threadIdx.x; i < SCAN_BLOCKS; i += 32)
            if (i < b) acc += d_blk[i];
        #pragma unroll
        for (int off = 16; off; off >>= 1) acc += __shfl_xor_sync(0xffffffffu, acc, off);
        if (threadIdx.x == 0) spref = acc;
    }
    __syncthreads();
    int pref = spref;
    int i = b * SCAN_CHUNK + threadIdx.x;
    if (i < N_NODES) {
        int r = d_rowptr[i] + pref;
        d_rowptr[i] = r;
        d_cursor[i] = r;                                 // fill cursor = row start
    }
    if (i == 0) d_rowptr[N_NODES] = N_EDGES;
}

__global__ void k_fill(const int* __restrict__ src, const int* __restrict__ dst,
                       const float* __restrict__ w) {
    int e = blockIdx.x * blockDim.x + threadIdx.x;
    if (e < N_EDGES) {
        int pos = atomicAdd(&d_cursor[dst[e]], 1);
        d_csr_sw[pos] = make_int2(src[e], __float_as_int(w[e]));
    }
}

// ---------------- GEMM1: pipelined fp16 mma.sync, fp16 output ----------------
#define A_PITCH   72                       // floats; 288B row (conflict-free LDS.64)
#define STG_A     0
#define STG_B     36864                    // 128*288
#define STG_STRIDE 53248                   // 36864 + 16384
#define C_STRIDE 132
#define SM_SZ    (2 * STG_STRIDE)          // 106496; C staging reuses

__global__ void __launch_bounds__(256, 2) k_gemm1_tc(const float* __restrict__ A) {
    extern __shared__ char smem[];
    const uint32_t sb = smem_u32(smem);
    const int tid = threadIdx.x, wid = tid >> 5, lid = tid & 31;
    const int m0 = blockIdx.x * 128;
    const int warp_m = wid >> 2, warp_n = wid & 3;
    const int g = lid >> 2, tq = lid & 3;

    float acc[4][4][4];
    #pragma unroll
    for (int i = 0; i < 4; i++)
        #pragma unroll
        for (int j = 0; j < 4; j++)
            #pragma unroll
            for (int r = 0; r < 4; r++) acc[i][j][r] = 0.f;

    const uint32_t a_lane_base = (uint32_t)((warp_m * 64 + g) * A_PITCH + 2 * tq) * 4;

    const int brow = warp_n * 32 + (lid & 7) + ((lid >> 4) << 3);
    const uint32_t b_rb = (uint32_t)brow * 128;
    const uint32_t b_rx = (uint32_t)((brow & 7) << 4);
    const uint32_t b_cl = (uint32_t)(((lid >> 3) & 1) << 4);

    auto load_chunk = [&](int kc, int s) {
        const int kbase = kc * 64;
        const uint32_t stg = sb + s * STG_STRIDE;
        #pragma unroll
        for (int i = 0; i < 8; i++) {
            int line = i * 256 + tid;
            int row = line >> 4, seg = line & 15;
            int m = m0 + row; if (m > N_NODES - 1) m = N_NODES - 1;
            cp_async16(stg + STG_A + row * (A_PITCH * 4) + seg * 16,
                       A + (size_t)m * NFEAT + kbase + seg * 4);
        }
        #pragma unroll
        for (int i = 0; i < 4; i++) {
            int line = i * 256 + tid;
            int n = line >> 3, seg = line & 7;
            uint32_t boff = (uint32_t)(n * 128 + seg * 16);
            uint32_t sw = boff ^ ((boff >> 3) & 0x70);
            cp_async16(stg + STG_B + sw,
                       d_W1T16 + (size_t)n * NFEAT + kbase + seg * 8);
        }
        asm volatile("cp.async.commit_group;" ::: "memory");
    };

    load_chunk(0, 0);

    for (int kc = 0; kc < NFEAT / 64; kc++) {
        if (kc < 7) {
            load_chunk(kc + 1, (kc + 1) & 1);
            asm volatile("cp.async.wait_group 1;" ::: "memory");
        } else {
            asm volatile("cp.async.wait_group 0;" ::: "memory");
        }
        __syncthreads();

        const uint32_t stg = sb + (kc & 1) * STG_STRIDE;
        const uint32_t aB = stg + STG_A + a_lane_base;

        #pragma unroll
        for (int ks = 0; ks < 4; ks++) {
            const uint32_t acol = (uint32_t)(ks * 16) * 4;
            const uint32_t bcb = (uint32_t)(ks * 32) + b_cl;
            const uint32_t boff = b_rb + (bcb ^ b_rx);

            uint32_t bf[2][4];
            #pragma unroll
            for (int np = 0; np < 2; np++)
                ldsm4(bf[np], stg + STG_B + boff + np * 2048);

            uint32_t af[4][4];
            #pragma unroll
            for (int mf = 0; mf < 4; mf++) {
                const uint32_t rb = aB + (uint32_t)(mf * 16 * A_PITCH) * 4 + acol;
                af[mf][0] = lds_cvt(rb);
                af[mf][1] = lds_cvt(rb + 8 * A_PITCH * 4);
                af[mf][2] = lds_cvt(rb + 8 * 4);
                af[mf][3] = lds_cvt(rb + 8 * A_PITCH * 4 + 8 * 4);
            }
            #pragma unroll
            for (int mf = 0; mf < 4; mf++)
                #pragma unroll
                for (int nf = 0; nf < 4; nf++)
                    mma_f16(acc[mf][nf], af[mf], &bf[nf >> 1][(nf & 1) * 2]);
        }
        __syncthreads();
    }

    float* sC = reinterpret_cast<float*>(smem);
    #pragma unroll
    for (int mf = 0; mf < 4; mf++) {
        int row = warp_m * 64 + mf * 16 + g;
        #pragma unroll
        for (int nf = 0; nf < 4; nf++) {
            int col = warp_n * 32 + nf * 8 + 2 * tq;
            *reinterpret_cast<float2*>(&sC[row * C_STRIDE + col]) =
                make_float2(acc[mf][nf][0], acc[mf][nf][1]);
            *reinterpret_cast<float2*>(&sC[(row + 8) * C_STRIDE + col]) =
                make_float2(acc[mf][nf][2], acc[mf][nf][3]);
        }
    }
    __syncthreads();
    #pragma unroll
    for (int r = 0; r < 16; r++) {
        int row = wid * 16 + r;
        int m = m0 + row;
        if (m < N_NODES) {
            float4 v = *reinterpret_cast<const float4*>(&sC[row * C_STRIDE + lid * 4]);
            __half2 h0 = __floats2half2_rn(v.x, v.y);
            __half2 h1 = __floats2half2_rn(v.z, v.w);
            uint2 u = make_uint2(*reinterpret_cast<uint32_t*>(&h0),
                                 *reinterpret_cast<uint32_t*>(&h1));
            *reinterpret_cast<uint2*>(d_H1h + (size_t)m * NHID + lid * 4) = u;
        }
    }
}

// ---------------- Aggregation layer 1 + bias + relu: warp per node (fp16 in/out) ----------------
__global__ void __launch_bounds__(256) k_agg1(const float* __restrict__ b1) {
    int node = blockIdx.x * 8 + (threadIdx.x >> 5);
    if (node >= N_NODES) return;
    int lane = threadIdx.x & 31;
    int beg = d_rowptr[node], end = d_rowptr[node + 1];
    float4 acc = make_float4(0.f, 0.f, 0.f, 0.f);
    int e = beg;
    for (; e + 1 < end; e += 2) {
        int2 sw0 = d_csr_sw[e];
        int2 sw1 = d_csr_sw[e + 1];
        float w0 = __int_as_float(sw0.y), w1 = __int_as_float(sw1.y);
        uint2 u0 = *reinterpret_cast<const uint2*>(d_H1h + (size_t)sw0.x * NHID + lane * 4);
        uint2 u1 = *reinterpret_cast<const uint2*>(d_H1h + (size_t)sw1.x * NHID + lane * 4);
        float2 a0 = h2f(u0.x), a1 = h2f(u0.y);
        float2 c0 = h2f(u1.x), c1 = h2f(u1.y);
        acc.x = fmaf(w0, a0.x, acc.x); acc.y = fmaf(w0, a0.y, acc.y);
        acc.z = fmaf(w0, a1.x, acc.z); acc.w = fmaf(w0, a1.y, acc.w);
        acc.x = fmaf(w1, c0.x, acc.x); acc.y = fmaf(w1, c0.y, acc.y);
        acc.z = fmaf(w1, c1.x, acc.z); acc.w = fmaf(w1, c1.y, acc.w);
    }
    if (e < end) {
        int2 sw0 = d_csr_sw[e];
        float w0 = __int_as_float(sw0.y);
        uint2 u0 = *reinterpret_cast<const uint2*>(d_H1h + (size_t)sw0.x * NHID + lane * 4);
        float2 a0 = h2f(u0.x), a1 = h2f(u0.y);
        acc.x = fmaf(w0, a0.x, acc.x); acc.y = fmaf(w0, a0.y, acc.y);
        acc.z = fmaf(w0, a1.x, acc.z); acc.w = fmaf(w0, a1.y, acc.w);
    }
    float4 bb = reinterpret_cast<const float4*>(b1)[lane];
    acc.x = fmaxf(acc.x + bb.x, 0.f);
    acc.y = fmaxf(acc.y + bb.y, 0.f);
    acc.z = fmaxf(acc.z + bb.z, 0.f);
    acc.w = fmaxf(acc.w + bb.w, 0.f);
    __half2 h0 = __floats2half2_rn(acc.x, acc.y);
    __half2 h1 = __floats2half2_rn(acc.z, acc.w);
    uint2 u = make_uint2(*reinterpret_cast<uint32_t*>(&h0),
                         *reinterpret_cast<uint32_t*>(&h1));
    *reinterpret_cast<uint2*>(d_X1h + (size_t)node * NHID + lane * 4) = u;
}

// ---------------- GEMM2: H2 = X1 @ W2, fp16 in/out, padded rows ----------------
__global__ void __launch_bounds__(256) k_gemm2(const float* __restrict__ W2) {
    __shared__ float w[NHID * NCLASS];   // [k][c], 20KB
    for (int i = threadIdx.x; i < NHID * NCLASS; i += 256) w[i] = W2[i];
    __syncthreads();

    int n = blockIdx.x * blockDim.x + threadIdx.x;
    if (n >= N_NODES) return;

    unsigned long long acc[NCLASS / 2];
    #pragma unroll
    for (int j = 0; j < NCLASS / 2; j++) acc[j] = 0ull;

    const uint4* xr = reinterpret_cast<const uint4*>(d_X1h + (size_t)n * NHID);
    #pragma unroll 2
    for (int kb = 0; kb < NHID / 8; kb++) {
        uint4 u = xr[kb];
        float2 f0 = h2f(u.x), f1 = h2f(u.y), f2 = h2f(u.z), f3 = h2f(u.w);
        float xs[8] = {f0.x, f0.y, f1.x, f1.y, f2.x, f2.y, f3.x, f3.y};
        #pragma unroll
        for (int q = 0; q < 8; q++) {
            int k = kb * 8 + q;
            unsigned long long xd = pk2(xs[q], xs[q]);
            const unsigned long long* wr =
                reinterpret_cast<const unsigned long long*>(&w[k * NCLASS]);
            #pragma unroll
            for (int j = 0; j < NCLASS / 2; j++) fma2(acc[j], xd, wr[j]);
        }
    }
    __half* o = d_H2h + (size_t)n * H2S;
    #pragma unroll
    for (int j = 0; j < NCLASS / 2; j++) {
        float2 p = upk(acc[j]);
        __half2 h = __floats2half2_rn(p.x, p.y);
        *reinterpret_cast<uint32_t*>(o + 2 * j) = *reinterpret_cast<uint32_t*>(&h);
    }
}

// ---------------- Aggregation layer 2 + bias + log_softmax: warp per node ----------------
__global__ void __launch_bounds__(256) k_agg2_lsm(const float* __restrict__ b2,
                                                  float* __restrict__ out) {
    int node = blockIdx.x * 8 + (threadIdx.x >> 5);
    if (node >= N_NODES) return;
    int lane = threadIdx.x & 31;
    bool has1 = lane < (NCLASS - 32);
    int beg = d_rowptr[node], end = d_rowptr[node + 1];
    float a0 = 0.f, a1 = 0.f;
    for (int e = beg; e < end; e++) {
        int2 sw = d_csr_sw[e];
        float w = __int_as_float(sw.y);
        const __half* r = d_H2h + (size_t)sw.x * H2S;
        a0 = fmaf(w, __half2float(r[lane]), a0);
        if (has1) a1 = fmaf(w, __half2float(r[32 + lane]), a1);
    }
    a0 += b2[lane];
    if (has1) a1 += b2[32 + lane];

    float m = has1 ? fmaxf(a0, a1) : a0;
    #pragma unroll
    for (int off = 16; off; off >>= 1) m = fmaxf(m, __shfl_xor_sync(0xffffffffu, m, off));
    float s = expf(a0 - m) + (has1 ? expf(a1 - m) : 0.f);
    #pragma unroll
    for (int off = 16; off; off >>= 1) s += __shfl_xor_sync(0xffffffffu, s, off);
    float l = m + logf(s);

    float* o = out + (size_t)node * NCLASS;
    o[lane] = a0 - l;
    if (has1) o[32 + lane] = a1 - l;
}

// ---------------- launch ----------------
extern "C" void kernel_launch(void* const* d_in, const int* in_sizes, int n_in,
                              void* d_out, int out_size) {
    const float* features = (const float*)d_in[0];
    const int*   edge_src = (const int*)d_in[1];
    const int*   edge_dst = (const int*)d_in[2];
    const float* edge_w   = (const float*)d_in[3];
    const float* W1       = (const float*)d_in[4];
    const float* b1       = (const float*)d_in[5];
    const float* W2       = (const float*)d_in[6];
    const float* b2       = (const float*)d_in[7];
    float* out = (float*)d_out;

    static bool attr_set = false;
    if (!attr_set) {
        cudaFuncSetAttribute(k_gemm1_tc, cudaFuncAttributeMaxDynamicSharedMemorySize, SM_SZ);
        attr_set = true;
    }

    // 9 launches; gemm1 kept 4th for the ncu capture slot.
    k_prep<<<392, 256>>>(W1);                                       // prepW + zero deg
    k_hist<<<(N_EDGES + 255) / 256, 256>>>(edge_dst);
    k_scan1<<<SCAN_BLOCKS, SCAN_CHUNK>>>();
    k_gemm1_tc<<<(N_NODES + 127) / 128, 256, SM_SZ>>>(features);    // 4th launch
    k_scan23<<<SCAN_BLOCKS, SCAN_CHUNK>>>();
    k_fill<<<(N_EDGES + 255) / 256, 256>>>(edge_src, edge_dst, edge_w);
    k_agg1<<<(N_NODES + 7) / 8, 256>>>(b1);
    k_gemm2<<<(N_NODES + 255) / 256, 256>>>(W2);
    k_agg2_lsm<<<(N_NODES + 7) / 8, 256>>>(b2, out);
}

// round 16
// speedup vs baseline: 1.0725x; 1.0725x over previous
#include <cuda_runtime.h>
#include <cuda_fp16.h>
#include <math.h>
#include <stdint.h>

#define N_NODES 100000
#define N_EDGES 1600000
#define NFEAT   512
#define NHID    128
#define NCLASS  40

// ---------------- static scratch (no allocation allowed) ----------------
__device__ __half d_H1h[(size_t)N_NODES * NHID];   // features @ W1   (fp16)
__device__ __half d_X1h[(size_t)N_NODES * NHID];   // relu(agg1+b1)   (fp16)
__device__ __half d_H2h[(size_t)N_NODES * NCLASS]; // X1 @ W2         (fp16)
__device__ int   d_deg[N_NODES];
__device__ int   d_cursor[N_NODES];
__device__ int   d_rowptr[N_NODES + 1];
__device__ int   d_blk[128];
__device__ int2  d_csr_sw[N_EDGES];               // {src, bits(weight)} packed
__device__ __half d_W1T16[(size_t)NHID * NFEAT];  // W1^T fp16, [n][k]

// ---------------- f32x2 helpers (packed dual-fp32 pipe) ----------------
__device__ __forceinline__ unsigned long long pk2(float x, float y) {
    unsigned long long r;
    asm("mov.b64 %0, {%1, %2};" : "=l"(r) : "f"(x), "f"(y));
    return r;
}
__device__ __forceinline__ void fma2(unsigned long long &d, unsigned long long a, unsigned long long b) {
    asm("fma.rn.f32x2 %0, %1, %2, %0;" : "+l"(d) : "l"(a), "l"(b));
}
__device__ __forceinline__ float2 upk(unsigned long long v) {
    float x, y;
    asm("mov.b64 {%0, %1}, %2;" : "=f"(x), "=f"(y) : "l"(v));
    return make_float2(x, y);
}

// ---------------- warp-mma helpers ----------------
__device__ __forceinline__ uint32_t smem_u32(const void* p) {
    uint32_t a;
    asm("{ .reg .u64 t; cvta.to.shared.u64 t, %1; cvt.u32.u64 %0, t; }" : "=r"(a) : "l"(p));
    return a;
}
__device__ __forceinline__ void ldsm4(uint32_t* r, uint32_t addr) {
    asm volatile("ldmatrix.sync.aligned.m8n8.x4.shared.b16 {%0,%1,%2,%3}, [%4];"
                 : "=r"(r[0]), "=r"(r[1]), "=r"(r[2]), "=r"(r[3]) : "r"(addr));
}
__device__ __forceinline__ void mma_f16(float* d, const uint32_t* a, const uint32_t* b) {
    asm volatile(
        "mma.sync.aligned.m16n8k16.row.col.f32.f16.f16.f32 "
        "{%0,%1,%2,%3}, {%4,%5,%6,%7}, {%8,%9}, {%0,%1,%2,%3};"
        : "+f"(d[0]), "+f"(d[1]), "+f"(d[2]), "+f"(d[3])
        : "r"(a[0]), "r"(a[1]), "r"(a[2]), "r"(a[3]), "r"(b[0]), "r"(b[1]));
}
__device__ __forceinline__ uint32_t lds_cvt(uint32_t addr) {
    float x, y;
    asm volatile("ld.shared.v2.f32 {%0,%1}, [%2];" : "=f"(x), "=f"(y) : "r"(addr));
    uint32_t r;
    asm("cvt.rn.f16x2.f32 %0, %1, %2;" : "=r"(r) : "f"(y), "f"(x));   // hi=y, lo=x
    return r;
}
__device__ __forceinline__ void cp_async16(uint32_t dst, const void* src) {
    asm volatile("cp.async.cg.shared.global [%0], [%1], 16;" :: "r"(dst), "l"(src));
}
__device__ __forceinline__ float2 h2f(uint32_t bits) {
    __half2 h = *reinterpret_cast<__half2*>(&bits);
    return __half22float2(h);
}

// ---------------- fused W1^T fp16 prep + degree zero ----------------
__global__ void k_prep(const float* __restrict__ W1) {
    int t = blockIdx.x * blockDim.x + threadIdx.x;
    if (t < NHID * (NFEAT / 8)) {
        int n  = t & (NHID - 1);
        int kb = t >> 7;
        __align__(16) __half h[8];
        #pragma unroll
        for (int j = 0; j < 8; j++)
            h[j] = __float2half_rn(W1[(size_t)(kb * 8 + j) * NHID + n]);
        *reinterpret_cast<uint4*>(d_W1T16 + (size_t)n * NFEAT + kb * 8) =
            *reinterpret_cast<uint4*>(h);
    }
    for (int i = t; i < N_NODES; i += gridDim.x * blockDim.x) d_deg[i] = 0;
}

__global__ void k_hist(const int* __restrict__ dst) {
    int e = blockIdx.x * blockDim.x + threadIdx.x;
    if (e < N_EDGES) atomicAdd(&d_deg[dst[e]], 1);
}

#define SCAN_CHUNK 1024
#define SCAN_BLOCKS ((N_NODES + SCAN_CHUNK - 1) / SCAN_CHUNK)   // 98

// shfl-based block scan (2 barriers)
__global__ void __launch_bounds__(SCAN_CHUNK) k_scan1() {
    __shared__ int wsum[32];
    int i = blockIdx.x * SCAN_CHUNK + threadIdx.x;
    int v = (i < N_NODES) ? d_deg[i] : 0;
    int lane = threadIdx.x & 31, w = threadIdx.x >> 5;
    int x = v;
    #pragma unroll
    for (int off = 1; off < 32; off <<= 1) {
        int y = __shfl_up_sync(0xffffffffu, x, off);
        if (lane >= off) x += y;
    }
    if (lane == 31) wsum[w] = x;
    __syncthreads();
    if (w == 0) {
        int s = wsum[lane];
        #pragma unroll
        for (int off = 1; off < 32; off <<= 1) {
            int y = __shfl_up_sync(0xffffffffu, s, off);
            if (lane >= off) s += y;
        }
        wsum[lane] = s;
    }
    __syncthreads();
    int incl = x + (w > 0 ? wsum[w - 1] : 0);
    if (i < N_NODES) d_rowptr[i] = incl - v;            // exclusive within block
    if (threadIdx.x == SCAN_CHUNK - 1) d_blk[blockIdx.x] = incl;
}

// fused scan2+scan3: per-block cross-block prefix + rowptr fixup + cursor init
__global__ void __launch_bounds__(SCAN_CHUNK) k_scan23() {
    __shared__ int spref;
    int b = blockIdx.x;
    if (threadIdx.x < 32) {
        int acc = 0;
        for (int i = threadIdx.x; i < SCAN_BLOCKS; i += 32)
            if (i < b) acc += d_blk[i];
        #pragma unroll
        for (int off = 16; off; off >>= 1) acc += __shfl_xor_sync(0xffffffffu, acc, off);
        if (threadIdx.x == 0) spref = acc;
    }
    __syncthreads();
    int pref = spref;
    int i = b * SCAN_CHUNK + threadIdx.x;
    if (i < N_NODES) {
        int r = d_rowptr[i] + pref;
        d_rowptr[i] = r;
        d_cursor[i] = r;                                 // fill cursor = row start
    }
    if (i == 0) d_rowptr[N_NODES] = N_EDGES;
}

__global__ void k_fill(const int* __restrict__ src, const int* __restrict__ dst,
                       const float* __restrict__ w) {
    int e = blockIdx.x * blockDim.x + threadIdx.x;
    if (e < N_EDGES) {
        int pos = atomicAdd(&d_cursor[dst[e]], 1);
        d_csr_sw[pos] = make_int2(src[e], __float_as_int(w[e]));
    }
}

// ---------------- GEMM1: pipelined fp16 mma.sync, fp16 output ----------------
#define A_PITCH   72                       // floats; 288B row (conflict-free LDS.64)
#define STG_A     0
#define STG_B     36864                    // 128*288
#define STG_STRIDE 53248                   // 36864 + 16384
#define C_STRIDE 132
#define SM_SZ    (2 * STG_STRIDE)          // 106496; C staging reuses

__global__ void __launch_bounds__(256, 2) k_gemm1_tc(const float* __restrict__ A) {
    extern __shared__ char smem[];
    const uint32_t sb = smem_u32(smem);
    const int tid = threadIdx.x, wid = tid >> 5, lid = tid & 31;
    const int m0 = blockIdx.x * 128;
    const int warp_m = wid >> 2, warp_n = wid & 3;
    const int g = lid >> 2, tq = lid & 3;

    float acc[4][4][4];
    #pragma unroll
    for (int i = 0; i < 4; i++)
        #pragma unroll
        for (int j = 0; j < 4; j++)
            #pragma unroll
            for (int r = 0; r < 4; r++) acc[i][j][r] = 0.f;

    const uint32_t a_lane_base = (uint32_t)((warp_m * 64 + g) * A_PITCH + 2 * tq) * 4;

    const int brow = warp_n * 32 + (lid & 7) + ((lid >> 4) << 3);
    const uint32_t b_rb = (uint32_t)brow * 128;
    const uint32_t b_rx = (uint32_t)((brow & 7) << 4);
    const uint32_t b_cl = (uint32_t)(((lid >> 3) & 1) << 4);

    auto load_chunk = [&](int kc, int s) {
        const int kbase = kc * 64;
        const uint32_t stg = sb + s * STG_STRIDE;
        #pragma unroll
        for (int i = 0; i < 8; i++) {
            int line = i * 256 + tid;
            int row = line >> 4, seg = line & 15;
            int m = m0 + row; if (m > N_NODES - 1) m = N_NODES - 1;
            cp_async16(stg + STG_A + row * (A_PITCH * 4) + seg * 16,
                       A + (size_t)m * NFEAT + kbase + seg * 4);
        }
        #pragma unroll
        for (int i = 0; i < 4; i++) {
            int line = i * 256 + tid;
            int n = line >> 3, seg = line & 7;
            uint32_t boff = (uint32_t)(n * 128 + seg * 16);
            uint32_t sw = boff ^ ((boff >> 3) & 0x70);
            cp_async16(stg + STG_B + sw,
                       d_W1T16 + (size_t)n * NFEAT + kbase + seg * 8);
        }
        asm volatile("cp.async.commit_group;" ::: "memory");
    };

    load_chunk(0, 0);

    for (int kc = 0; kc < NFEAT / 64; kc++) {
        if (kc < 7) {
            load_chunk(kc + 1, (kc + 1) & 1);
            asm volatile("cp.async.wait_group 1;" ::: "memory");
        } else {
            asm volatile("cp.async.wait_group 0;" ::: "memory");
        }
        __syncthreads();

        const uint32_t stg = sb + (kc & 1) * STG_STRIDE;
        const uint32_t aB = stg + STG_A + a_lane_base;

        #pragma unroll
        for (int ks = 0; ks < 4; ks++) {
            const uint32_t acol = (uint32_t)(ks * 16) * 4;
            const uint32_t bcb = (uint32_t)(ks * 32) + b_cl;
            const uint32_t boff = b_rb + (bcb ^ b_rx);

            uint32_t bf[2][4];
            #pragma unroll
            for (int np = 0; np < 2; np++)
                ldsm4(bf[np], stg + STG_B + boff + np * 2048);

            uint32_t af[4][4];
            #pragma unroll
            for (int mf = 0; mf < 4; mf++) {
                const uint32_t rb = aB + (uint32_t)(mf * 16 * A_PITCH) * 4 + acol;
                af[mf][0] = lds_cvt(rb);
                af[mf][1] = lds_cvt(rb + 8 * A_PITCH * 4);
                af[mf][2] = lds_cvt(rb + 8 * 4);
                af[mf][3] = lds_cvt(rb + 8 * A_PITCH * 4 + 8 * 4);
            }
            #pragma unroll
            for (int mf = 0; mf < 4; mf++)
                #pragma unroll
                for (int nf = 0; nf < 4; nf++)
                    mma_f16(acc[mf][nf], af[mf], &bf[nf >> 1][(nf & 1) * 2]);
        }
        __syncthreads();
    }

    float* sC = reinterpret_cast<float*>(smem);
    #pragma unroll
    for (int mf = 0; mf < 4; mf++) {
        int row = warp_m * 64 + mf * 16 + g;
        #pragma unroll
        for (int nf = 0; nf < 4; nf++) {
            int col = warp_n * 32 + nf * 8 + 2 * tq;
            *reinterpret_cast<float2*>(&sC[row * C_STRIDE + col]) =
                make_float2(acc[mf][nf][0], acc[mf][nf][1]);
            *reinterpret_cast<float2*>(&sC[(row + 8) * C_STRIDE + col]) =
                make_float2(acc[mf][nf][2], acc[mf][nf][3]);
        }
    }
    __syncthreads();
    #pragma unroll
    for (int r = 0; r < 16; r++) {
        int row = wid * 16 + r;
        int m = m0 + row;
        if (m < N_NODES) {
            float4 v = *reinterpret_cast<const float4*>(&sC[row * C_STRIDE + lid * 4]);
            __half2 h0 = __floats2half2_rn(v.x, v.y);
            __half2 h1 = __floats2half2_rn(v.z, v.w);
            uint2 u = make_uint2(*reinterpret_cast<uint32_t*>(&h0),
                                 *reinterpret_cast<uint32_t*>(&h1));
            *reinterpret_cast<uint2*>(d_H1h + (size_t)m * NHID + lid * 4) = u;
        }
    }
}

// ---------------- Aggregation layer 1 + bias + relu: warp per node (fp16 in/out) ----------------
__global__ void __launch_bounds__(256) k_agg1(const float* __restrict__ b1) {
    int node = blockIdx.x * 8 + (threadIdx.x >> 5);
    if (node >= N_NODES) return;
    int lane = threadIdx.x & 31;
    int beg = d_rowptr[node], end = d_rowptr[node + 1];
    float4 acc = make_float4(0.f, 0.f, 0.f, 0.f);
    int e = beg;
    for (; e + 1 < end; e += 2) {
        int2 sw0 = d_csr_sw[e];
        int2 sw1 = d_csr_sw[e + 1];
        float w0 = __int_as_float(sw0.y), w1 = __int_as_float(sw1.y);
        uint2 u0 = *reinterpret_cast<const uint2*>(d_H1h + (size_t)sw0.x * NHID + lane * 4);
        uint2 u1 = *reinterpret_cast<const uint2*>(d_H1h + (size_t)sw1.x * NHID + lane * 4);
        float2 a0 = h2f(u0.x), a1 = h2f(u0.y);
        float2 c0 = h2f(u1.x), c1 = h2f(u1.y);
        acc.x = fmaf(w0, a0.x, acc.x); acc.y = fmaf(w0, a0.y, acc.y);
        acc.z = fmaf(w0, a1.x, acc.z); acc.w = fmaf(w0, a1.y, acc.w);
        acc.x = fmaf(w1, c0.x, acc.x); acc.y = fmaf(w1, c0.y, acc.y);
        acc.z = fmaf(w1, c1.x, acc.z); acc.w = fmaf(w1, c1.y, acc.w);
    }
    if (e < end) {
        int2 sw0 = d_csr_sw[e];
        float w0 = __int_as_float(sw0.y);
        uint2 u0 = *reinterpret_cast<const uint2*>(d_H1h + (size_t)sw0.x * NHID + lane * 4);
        float2 a0 = h2f(u0.x), a1 = h2f(u0.y);
        acc.x = fmaf(w0, a0.x, acc.x); acc.y = fmaf(w0, a0.y, acc.y);
        acc.z = fmaf(w0, a1.x, acc.z); acc.w = fmaf(w0, a1.y, acc.w);
    }
    float4 bb = reinterpret_cast<const float4*>(b1)[lane];
    acc.x = fmaxf(acc.x + bb.x, 0.f);
    acc.y = fmaxf(acc.y + bb.y, 0.f);
    acc.z = fmaxf(acc.z + bb.z, 0.f);
    acc.w = fmaxf(acc.w + bb.w, 0.f);
    __half2 h0 = __floats2half2_rn(acc.x, acc.y);
    __half2 h1 = __floats2half2_rn(acc.z, acc.w);
    uint2 u = make_uint2(*reinterpret_cast<uint32_t*>(&h0),
                         *reinterpret_cast<uint32_t*>(&h1));
    *reinterpret_cast<uint2*>(d_X1h + (size_t)node * NHID + lane * 4) = u;
}

// ---------------- GEMM2: H2 = X1 @ W2, fp16 in/out ----------------
__global__ void __launch_bounds__(256) k_gemm2(const float* __restrict__ W2) {
    __shared__ float w[NHID * NCLASS];   // [k][c], 20KB
    for (int i = threadIdx.x; i < NHID * NCLASS; i += 256) w[i] = W2[i];
    __syncthreads();

    int n = blockIdx.x * blockDim.x + threadIdx.x;
    if (n >= N_NODES) return;

    unsigned long long acc[NCLASS / 2];
    #pragma unroll
    for (int j = 0; j < NCLASS / 2; j++) acc[j] = 0ull;

    const uint4* xr = reinterpret_cast<const uint4*>(d_X1h + (size_t)n * NHID);
    #pragma unroll 2
    for (int kb = 0; kb < NHID / 8; kb++) {
        uint4 u = xr[kb];
        float2 f0 = h2f(u.x), f1 = h2f(u.y), f2 = h2f(u.z), f3 = h2f(u.w);
        float xs[8] = {f0.x, f0.y, f1.x, f1.y, f2.x, f2.y, f3.x, f3.y};
        #pragma unroll
        for (int q = 0; q < 8; q++) {
            int k = kb * 8 + q;
            unsigned long long xd = pk2(xs[q], xs[q]);
            const unsigned long long* wr =
                reinterpret_cast<const unsigned long long*>(&w[k * NCLASS]);
            #pragma unroll
            for (int j = 0; j < NCLASS / 2; j++) fma2(acc[j], xd, wr[j]);
        }
    }
    __half* o = d_H2h + (size_t)n * NCLASS;
    #pragma unroll
    for (int j = 0; j < NCLASS / 2; j++) {
        float2 p = upk(acc[j]);
        __half2 h = __floats2half2_rn(p.x, p.y);
        *reinterpret_cast<uint32_t*>(o + 2 * j) = *reinterpret_cast<uint32_t*>(&h);
    }
}

// ---------------- Aggregation layer 2 + bias + log_softmax: warp per node ----------------
__global__ void __launch_bounds__(256) k_agg2_lsm(const float* __restrict__ b2,
                                                  float* __restrict__ out) {
    int node = blockIdx.x * 8 + (threadIdx.x >> 5);
    if (node >= N_NODES) return;
    int lane = threadIdx.x & 31;
    bool has1 = lane < (NCLASS - 32);
    int beg = d_rowptr[node], end = d_rowptr[node + 1];
    float a0 = 0.f, a1 = 0.f;
    for (int e = beg; e < end; e++) {
        int2 sw = d_csr_sw[e];
        float w = __int_as_float(sw.y);
        const __half* r = d_H2h + (size_t)sw.x * NCLASS;
        a0 = fmaf(w, __half2float(r[lane]), a0);
        if (has1) a1 = fmaf(w, __half2float(r[32 + lane]), a1);
    }
    a0 += b2[lane];
    if (has1) a1 += b2[32 + lane];

    float m = has1 ? fmaxf(a0, a1) : a0;
    #pragma unroll
    for (int off = 16; off; off >>= 1) m = fmaxf(m, __shfl_xor_sync(0xffffffffu, m, off));
    float s = expf(a0 - m) + (has1 ? expf(a1 - m) : 0.f);
    #pragma unroll
    for (int off = 16; off; off >>= 1) s += __shfl_xor_sync(0xffffffffu, s, off);
    float l = m + logf(s);

    float* o = out + (size_t)node * NCLASS;
    o[lane] = a0 - l;
    if (has1) o[32 + lane] = a1 - l;
}

// ---------------- launch: forked graph (CSR chain || W-prep+GEMM1) ----------------
extern "C" void kernel_launch(void* const* d_in, const int* in_sizes, int n_in,
                              void* d_out, int out_size) {
    const float* features = (const float*)d_in[0];
    const int*   edge_src = (const int*)d_in[1];
    const int*   edge_dst = (const int*)d_in[2];
    const float* edge_w   = (const float*)d_in[3];
    const float* W1       = (const float*)d_in[4];
    const float* b1       = (const float*)d_in[5];
    const float* W2       = (const float*)d_in[6];
    const float* b2       = (const float*)d_in[7];
    float* out = (float*)d_out;

    static cudaStream_t sA = nullptr;
    static cudaEvent_t  eFork = nullptr, eJoin = nullptr;
    if (!sA) {
        cudaStreamCreateWithFlags(&sA, cudaStreamNonBlocking);
        cudaEventCreateWithFlags(&eFork, cudaEventDisableTiming);
        cudaEventCreateWithFlags(&eJoin, cudaEventDisableTiming);
        cudaFuncSetAttribute(k_gemm1_tc, cudaFuncAttributeMaxDynamicSharedMemorySize, SM_SZ);
    }

    // main: prep (W1T + zero deg) — both branches depend on it
    k_prep<<<392, 256>>>(W1);                                           // launch 1
    cudaEventRecord(eFork, 0);
    cudaStreamWaitEvent(sA, eFork, 0);

    // side branch: CSR build (atomics/L2-bound)
    k_hist<<<(N_EDGES + 255) / 256, 256, 0, sA>>>(edge_dst);            // launch 2
    k_scan1<<<SCAN_BLOCKS, SCAN_CHUNK, 0, sA>>>();                      // launch 3

    // main branch: GEMM1 (DRAM/tensor-bound) — 4th launch, ncu slot
    k_gemm1_tc<<<(N_NODES + 127) / 128, 256, SM_SZ>>>(features);        // launch 4

    k_scan23<<<SCAN_BLOCKS, SCAN_CHUNK, 0, sA>>>();                     // launch 5
    k_fill<<<(N_EDGES + 255) / 256, 256, 0, sA>>>(edge_src, edge_dst, edge_w); // launch 6
    cudaEventRecord(eJoin, sA);
    cudaStreamWaitEvent(0, eJoin, 0);

    // joined tail
    k_agg1<<<(N_NODES + 7) / 8, 256>>>(b1);                             // launch 7
    k_gemm2<<<(N_NODES + 255) / 256, 256>>>(W2);                        // launch 8
    k_agg2_lsm<<<(N_NODES + 7) / 8, 256>>>(b2, out);                    // launch 9
}

// round 17
// speedup vs baseline: 1.0782x; 1.0053x over previous
#include <cuda_runtime.h>
#include <cuda_fp16.h>
#include <math.h>
#include <stdint.h>

#define N_NODES 100000
#define N_EDGES 1600000
#define NFEAT   512
#define NHID    128
#define NCLASS  40

// ---------------- static scratch (no allocation allowed) ----------------
__device__ __half d_H1h[(size_t)N_NODES * NHID];   // features @ W1   (fp16)
__device__ __half d_X1h[(size_t)N_NODES * NHID];   // relu(agg1+b1)   (fp16)
__device__ __half d_H2h[(size_t)N_NODES * NCLASS]; // X1 @ W2         (fp16)
__device__ int   d_deg[N_NODES];
__device__ int   d_cursor[N_NODES];
__device__ int   d_rowptr[N_NODES + 1];
__device__ int   d_blk[128];
__device__ int2  d_csr_sw[N_EDGES];               // {src, bits(weight)} packed
__device__ __half d_W1T16[(size_t)NHID * NFEAT];  // W1^T fp16, [n][k]

// ---------------- f32x2 helpers (packed dual-fp32 pipe) ----------------
__device__ __forceinline__ unsigned long long pk2(float x, float y) {
    unsigned long long r;
    asm("mov.b64 %0, {%1, %2};" : "=l"(r) : "f"(x), "f"(y));
    return r;
}
__device__ __forceinline__ void fma2(unsigned long long &d, unsigned long long a, unsigned long long b) {
    asm("fma.rn.f32x2 %0, %1, %2, %0;" : "+l"(d) : "l"(a), "l"(b));
}
__device__ __forceinline__ float2 upk(unsigned long long v) {
    float x, y;
    asm("mov.b64 {%0, %1}, %2;" : "=f"(x), "=f"(y) : "l"(v));
    return make_float2(x, y);
}

// ---------------- warp-mma helpers ----------------
__device__ __forceinline__ uint32_t smem_u32(const void* p) {
    uint32_t a;
    asm("{ .reg .u64 t; cvta.to.shared.u64 t, %1; cvt.u32.u64 %0, t; }" : "=r"(a) : "l"(p));
    return a;
}
__device__ __forceinline__ void ldsm4(uint32_t* r, uint32_t addr) {
    asm volatile("ldmatrix.sync.aligned.m8n8.x4.shared.b16 {%0,%1,%2,%3}, [%4];"
                 : "=r"(r[0]), "=r"(r[1]), "=r"(r[2]), "=r"(r[3]) : "r"(addr));
}
__device__ __forceinline__ void mma_f16(float* d, const uint32_t* a, const uint32_t* b) {
    asm volatile(
        "mma.sync.aligned.m16n8k16.row.col.f32.f16.f16.f32 "
        "{%0,%1,%2,%3}, {%4,%5,%6,%7}, {%8,%9}, {%0,%1,%2,%3};"
        : "+f"(d[0]), "+f"(d[1]), "+f"(d[2]), "+f"(d[3])
        : "r"(a[0]), "r"(a[1]), "r"(a[2]), "r"(a[3]), "r"(b[0]), "r"(b[1]));
}
__device__ __forceinline__ uint32_t lds_cvt(uint32_t addr) {
    float x, y;
    asm volatile("ld.shared.v2.f32 {%0,%1}, [%2];" : "=f"(x), "=f"(y) : "r"(addr));
    uint32_t r;
    asm("cvt.rn.f16x2.f32 %0, %1, %2;" : "=r"(r) : "f"(y), "f"(x));   // hi=y, lo=x
    return r;
}
__device__ __forceinline__ void cp_async16(uint32_t dst, const void* src) {
    asm volatile("cp.async.cg.shared.global [%0], [%1], 16;" :: "r"(dst), "l"(src));
}
__device__ __forceinline__ float2 h2f(uint32_t bits) {
    __half2 h = *reinterpret_cast<__half2*>(&bits);
    return __half22float2(h);
}

// ---------------- fused W1^T fp16 prep + degree zero ----------------
__global__ void k_prep(const float* __restrict__ W1) {
    int t = blockIdx.x * blockDim.x + threadIdx.x;
    if (t < NHID * (NFEAT / 8)) {
        int n  = t & (NHID - 1);
        int kb = t >> 7;
        __align__(16) __half h[8];
        #pragma unroll
        for (int j = 0; j < 8; j++)
            h[j] = __float2half_rn(W1[(size_t)(kb * 8 + j) * NHID + n]);
        *reinterpret_cast<uint4*>(d_W1T16 + (size_t)n * NFEAT + kb * 8) =
            *reinterpret_cast<uint4*>(h);
    }
    for (int i = t; i < N_NODES; i += gridDim.x * blockDim.x) d_deg[i] = 0;
}

__global__ void k_hist(const int* __restrict__ dst) {
    int e = blockIdx.x * blockDim.x + threadIdx.x;
    if (e < N_EDGES) atomicAdd(&d_deg[dst[e]], 1);
}

#define SCAN_CHUNK 1024
#define SCAN_BLOCKS ((N_NODES + SCAN_CHUNK - 1) / SCAN_CHUNK)   // 98

// shfl-based block scan (2 barriers)
__global__ void __launch_bounds__(SCAN_CHUNK) k_scan1() {
    __shared__ int wsum[32];
    int i = blockIdx.x * SCAN_CHUNK + threadIdx.x;
    int v = (i < N_NODES) ? d_deg[i] : 0;
    int lane = threadIdx.x & 31, w = threadIdx.x >> 5;
    int x = v;
    #pragma unroll
    for (int off = 1; off < 32; off <<= 1) {
        int y = __shfl_up_sync(0xffffffffu, x, off);
        if (lane >= off) x += y;
    }
    if (lane == 31) wsum[w] = x;
    __syncthreads();
    if (w == 0) {
        int s = wsum[lane];
        #pragma unroll
        for (int off = 1; off < 32; off <<= 1) {
            int y = __shfl_up_sync(0xffffffffu, s, off);
            if (lane >= off) s += y;
        }
        wsum[lane] = s;
    }
    __syncthreads();
    int incl = x + (w > 0 ? wsum[w - 1] : 0);
    if (i < N_NODES) d_rowptr[i] = incl - v;            // exclusive within block
    if (threadIdx.x == SCAN_CHUNK - 1) d_blk[blockIdx.x] = incl;
}

// fused scan2+scan3: per-block cross-block prefix + rowptr fixup + cursor init
__global__ void __launch_bounds__(SCAN_CHUNK) k_scan23() {
    __shared__ int spref;
    int b = blockIdx.x;
    if (threadIdx.x < 32) {
        int acc = 0;
        for (int i = threadIdx.x; i < SCAN_BLOCKS; i += 32)
            if (i < b) acc += d_blk[i];
        #pragma unroll
        for (int off = 16; off; off >>= 1) acc += __shfl_xor_sync(0xffffffffu, acc, off);
        if (threadIdx.x == 0) spref = acc;
    }
    __syncthreads();
    int pref = spref;
    int i = b * SCAN_CHUNK + threadIdx.x;
    if (i < N_NODES) {
        int r = d_rowptr[i] + pref;
        d_rowptr[i] = r;
        d_cursor[i] = r;                                 // fill cursor = row start
    }
    if (i == 0) d_rowptr[N_NODES] = N_EDGES;
}

__global__ void k_fill(const int* __restrict__ src, const int* __restrict__ dst,
                       const float* __restrict__ w) {
    int e = blockIdx.x * blockDim.x + threadIdx.x;
    if (e < N_EDGES) {
        int pos = atomicAdd(&d_cursor[dst[e]], 1);
        d_csr_sw[pos] = make_int2(src[e], __float_as_int(w[e]));
    }
}

// ---------------- GEMM1: pipelined fp16 mma.sync, fp16 output ----------------
#define A_PITCH   72                       // floats; 288B row (conflict-free LDS.64)
#define STG_A     0
#define STG_B     36864                    // 128*288
#define STG_STRIDE 53248                   // 36864 + 16384
#define C_STRIDE 132
#define SM_SZ    (2 * STG_STRIDE)          // 106496; C staging reuses

__global__ void __launch_bounds__(256, 2) k_gemm1_tc(const float* __restrict__ A) {
    extern __shared__ char smem[];
    const uint32_t sb = smem_u32(smem);
    const int tid = threadIdx.x, wid = tid >> 5, lid = tid & 31;
    const int m0 = blockIdx.x * 128;
    const int warp_m = wid >> 2, warp_n = wid & 3;
    const int g = lid >> 2, tq = lid & 3;

    float acc[4][4][4];
    #pragma unroll
    for (int i = 0; i < 4; i++)
        #pragma unroll
        for (int j = 0; j < 4; j++)
            #pragma unroll
            for (int r = 0; r < 4; r++) acc[i][j][r] = 0.f;

    const uint32_t a_lane_base = (uint32_t)((warp_m * 64 + g) * A_PITCH + 2 * tq) * 4;

    const int brow = warp_n * 32 + (lid & 7) + ((lid >> 4) << 3);
    const uint32_t b_rb = (uint32_t)brow * 128;
    const uint32_t b_rx = (uint32_t)((brow & 7) << 4);
    const uint32_t b_cl = (uint32_t)(((lid >> 3) & 1) << 4);

    auto load_chunk = [&](int kc, int s) {
        const int kbase = kc * 64;
        const uint32_t stg = sb + s * STG_STRIDE;
        #pragma unroll
        for (int i = 0; i < 8; i++) {
            int line = i * 256 + tid;
            int row = line >> 4, seg = line & 15;
            int m = m0 + row; if (m > N_NODES - 1) m = N_NODES - 1;
            cp_async16(stg + STG_A + row * (A_PITCH * 4) + seg * 16,
                       A + (size_t)m * NFEAT + kbase + seg * 4);
        }
        #pragma unroll
        for (int i = 0; i < 4; i++) {
            int line = i * 256 + tid;
            int n = line >> 3, seg = line & 7;
            uint32_t boff = (uint32_t)(n * 128 + seg * 16);
            uint32_t sw = boff ^ ((boff >> 3) & 0x70);
            cp_async16(stg + STG_B + sw,
                       d_W1T16 + (size_t)n * NFEAT + kbase + seg * 8);
        }
        asm volatile("cp.async.commit_group;" ::: "memory");
    };

    load_chunk(0, 0);

    for (int kc = 0; kc < NFEAT / 64; kc++) {
        if (kc < 7) {
            load_chunk(kc + 1, (kc + 1) & 1);
            asm volatile("cp.async.wait_group 1;" ::: "memory");
        } else {
            asm volatile("cp.async.wait_group 0;" ::: "memory");
        }
        __syncthreads();

        const uint32_t stg = sb + (kc & 1) * STG_STRIDE;
        const uint32_t aB = stg + STG_A + a_lane_base;

        #pragma unroll
        for (int ks = 0; ks < 4; ks++) {
            const uint32_t acol = (uint32_t)(ks * 16) * 4;
            const uint32_t bcb = (uint32_t)(ks * 32) + b_cl;
            const uint32_t boff = b_rb + (bcb ^ b_rx);

            uint32_t bf[2][4];
            #pragma unroll
            for (int np = 0; np < 2; np++)
                ldsm4(bf[np], stg + STG_B + boff + np * 2048);

            uint32_t af[4][4];
            #pragma unroll
            for (int mf = 0; mf < 4; mf++) {
                const uint32_t rb = aB + (uint32_t)(mf * 16 * A_PITCH) * 4 + acol;
                af[mf][0] = lds_cvt(rb);
                af[mf][1] = lds_cvt(rb + 8 * A_PITCH * 4);
                af[mf][2] = lds_cvt(rb + 8 * 4);
                af[mf][3] = lds_cvt(rb + 8 * A_PITCH * 4 + 8 * 4);
            }
            #pragma unroll
            for (int mf = 0; mf < 4; mf++)
                #pragma unroll
                for (int nf = 0; nf < 4; nf++)
                    mma_f16(acc[mf][nf], af[mf], &bf[nf >> 1][(nf & 1) * 2]);
        }
        __syncthreads();
    }

    float* sC = reinterpret_cast<float*>(smem);
    #pragma unroll
    for (int mf = 0; mf < 4; mf++) {
        int row = warp_m * 64 + mf * 16 + g;
        #pragma unroll
        for (int nf = 0; nf < 4; nf++) {
            int col = warp_n * 32 + nf * 8 + 2 * tq;
            *reinterpret_cast<float2*>(&sC[row * C_STRIDE + col]) =
                make_float2(acc[mf][nf][0], acc[mf][nf][1]);
            *reinterpret_cast<float2*>(&sC[(row + 8) * C_STRIDE + col]) =
                make_float2(acc[mf][nf][2], acc[mf][nf][3]);
        }
    }
    __syncthreads();
    #pragma unroll
    for (int r = 0; r < 16; r++) {
        int row = wid * 16 + r;
        int m = m0 + row;
        if (m < N_NODES) {
            float4 v = *reinterpret_cast<const float4*>(&sC[row * C_STRIDE + lid * 4]);
            __half2 h0 = __floats2half2_rn(v.x, v.y);
            __half2 h1 = __floats2half2_rn(v.z, v.w);
            uint2 u = make_uint2(*reinterpret_cast<uint32_t*>(&h0),
                                 *reinterpret_cast<uint32_t*>(&h1));
            *reinterpret_cast<uint2*>(d_H1h + (size_t)m * NHID + lid * 4) = u;
        }
    }
}

// ---------------- Aggregation layer 1 + bias + relu: warp per node (fp16 in/out) ----------------
__global__ void __launch_bounds__(256) k_agg1(const float* __restrict__ b1) {
    int node = blockIdx.x * 8 + (threadIdx.x >> 5);
    if (node >= N_NODES) return;
    int lane = threadIdx.x & 31;
    int beg = d_rowptr[node], end = d_rowptr[node + 1];
    float4 acc = make_float4(0.f, 0.f, 0.f, 0.f);
    int e = beg;
    for (; e + 1 < end; e += 2) {
        int2 sw0 = d_csr_sw[e];
        int2 sw1 = d_csr_sw[e + 1];
        float w0 = __int_as_float(sw0.y), w1 = __int_as_float(sw1.y);
        uint2 u0 = *reinterpret_cast<const uint2*>(d_H1h + (size_t)sw0.x * NHID + lane * 4);
        uint2 u1 = *reinterpret_cast<const uint2*>(d_H1h + (size_t)sw1.x * NHID + lane * 4);
        float2 a0 = h2f(u0.x), a1 = h2f(u0.y);
        float2 c0 = h2f(u1.x), c1 = h2f(u1.y);
        acc.x = fmaf(w0, a0.x, acc.x); acc.y = fmaf(w0, a0.y, acc.y);
        acc.z = fmaf(w0, a1.x, acc.z); acc.w = fmaf(w0, a1.y, acc.w);
        acc.x = fmaf(w1, c0.x, acc.x); acc.y = fmaf(w1, c0.y, acc.y);
        acc.z = fmaf(w1, c1.x, acc.z); acc.w = fmaf(w1, c1.y, acc.w);
    }
    if (e < end) {
        int2 sw0 = d_csr_sw[e];
        float w0 = __int_as_float(sw0.y);
        uint2 u0 = *reinterpret_cast<const uint2*>(d_H1h + (size_t)sw0.x * NHID + lane * 4);
        float2 a0 = h2f(u0.x), a1 = h2f(u0.y);
        acc.x = fmaf(w0, a0.x, acc.x); acc.y = fmaf(w0, a0.y, acc.y);
        acc.z = fmaf(w0, a1.x, acc.z); acc.w = fmaf(w0, a1.y, acc.w);
    }
    float4 bb = reinterpret_cast<const float4*>(b1)[lane];
    acc.x = fmaxf(acc.x + bb.x, 0.f);
    acc.y = fmaxf(acc.y + bb.y, 0.f);
    acc.z = fmaxf(acc.z + bb.z, 0.f);
    acc.w = fmaxf(acc.w + bb.w, 0.f);
    __half2 h0 = __floats2half2_rn(acc.x, acc.y);
    __half2 h1 = __floats2half2_rn(acc.z, acc.w);
    uint2 u = make_uint2(*reinterpret_cast<uint32_t*>(&h0),
                         *reinterpret_cast<uint32_t*>(&h1));
    *reinterpret_cast<uint2*>(d_X1h + (size_t)node * NHID + lane * 4) = u;
}

// ---------------- GEMM2: H2 = X1 @ W2, fp16 in/out ----------------
__global__ void __launch_bounds__(256) k_gemm2(const float* __restrict__ W2) {
    __shared__ float w[NHID * NCLASS];   // [k][c], 20KB
    for (int i = threadIdx.x; i < NHID * NCLASS; i += 256) w[i] = W2[i];
    __syncthreads();

    int n = blockIdx.x * blockDim.x + threadIdx.x;
    if (n >= N_NODES) return;

    unsigned long long acc[NCLASS / 2];
    #pragma unroll
    for (int j = 0; j < NCLASS / 2; j++) acc[j] = 0ull;

    const uint4* xr = reinterpret_cast<const uint4*>(d_X1h + (size_t)n * NHID);
    #pragma unroll 2
    for (int kb = 0; kb < NHID / 8; kb++) {
        uint4 u = xr[kb];
        float2 f0 = h2f(u.x), f1 = h2f(u.y), f2 = h2f(u.z), f3 = h2f(u.w);
        float xs[8] = {f0.x, f0.y, f1.x, f1.y, f2.x, f2.y, f3.x, f3.y};
        #pragma unroll
        for (int q = 0; q < 8; q++) {
            int k = kb * 8 + q;
            unsigned long long xd = pk2(xs[q], xs[q]);
            const unsigned long long* wr =
                reinterpret_cast<const unsigned long long*>(&w[k * NCLASS]);
            #pragma unroll
            for (int j = 0; j < NCLASS / 2; j++) fma2(acc[j], xd, wr[j]);
        }
    }
    __half* o = d_H2h + (size_t)n * NCLASS;
    #pragma unroll
    for (int j = 0; j < NCLASS / 2; j++) {
        float2 p = upk(acc[j]);
        __half2 h = __floats2half2_rn(p.x, p.y);
        *reinterpret_cast<uint32_t*>(o + 2 * j) = *reinterpret_cast<uint32_t*>(&h);
    }
}

// ---------------- Aggregation layer 2 + bias + log_softmax: warp per node ----------------
__global__ void __launch_bounds__(256) k_agg2_lsm(const float* __restrict__ b2,
                                                  float* __restrict__ out) {
    int node = blockIdx.x * 8 + (threadIdx.x >> 5);
    if (node >= N_NODES) return;
    int lane = threadIdx.x & 31;
    bool has1 = lane < (NCLASS - 32);
    int beg = d_rowptr[node], end = d_rowptr[node + 1];
    float a0 = 0.f, a1 = 0.f;
    for (int e = beg; e < end; e++) {
        int2 sw = d_csr_sw[e];
        float w = __int_as_float(sw.y);
        const __half* r = d_H2h + (size_t)sw.x * NCLASS;
        a0 = fmaf(w, __half2float(r[lane]), a0);
        if (has1) a1 = fmaf(w, __half2float(r[32 + lane]), a1);
    }
    a0 += b2[lane];
    if (has1) a1 += b2[32 + lane];

    float m = has1 ? fmaxf(a0, a1) : a0;
    #pragma unroll
    for (int off = 16; off; off >>= 1) m = fmaxf(m, __shfl_xor_sync(0xffffffffu, m, off));
    float s = expf(a0 - m) + (has1 ? expf(a1 - m) : 0.f);
    #pragma unroll
    for (int off = 16; off; off >>= 1) s += __shfl_xor_sync(0xffffffffu, s, off);
    float l = m + logf(s);

    float* o = out + (size_t)node * NCLASS;
    o[lane] = a0 - l;
    if (has1) o[32 + lane] = a1 - l;
}

// ---------------- launch: forked graph (CSR chain || W-prep+GEMM1) ----------------
extern "C" void kernel_launch(void* const* d_in, const int* in_sizes, int n_in,
                              void* d_out, int out_size) {
    const float* features = (const float*)d_in[0];
    const int*   edge_src = (const int*)d_in[1];
    const int*   edge_dst = (const int*)d_in[2];
    const float* edge_w   = (const float*)d_in[3];
    const float* W1       = (const float*)d_in[4];
    const float* b1       = (const float*)d_in[5];
    const float* W2       = (const float*)d_in[6];
    const float* b2       = (const float*)d_in[7];
    float* out = (float*)d_out;

    static cudaStream_t sA = nullptr;
    static cudaEvent_t  eFork = nullptr, eJoin = nullptr;
    if (!sA) {
        cudaStreamCreateWithFlags(&sA, cudaStreamNonBlocking);
        cudaEventCreateWithFlags(&eFork, cudaEventDisableTiming);
        cudaEventCreateWithFlags(&eJoin, cudaEventDisableTiming);
        cudaFuncSetAttribute(k_gemm1_tc, cudaFuncAttributeMaxDynamicSharedMemorySize, SM_SZ);
    }

    // main: prep (W1T + zero deg) — both branches depend on it
    k_prep<<<392, 256>>>(W1);                                           // launch 1
    cudaEventRecord(eFork, 0);
    cudaStreamWaitEvent(sA, eFork, 0);

    // side branch: CSR build (atomics/L2-bound)
    k_hist<<<(N_EDGES + 255) / 256, 256, 0, sA>>>(edge_dst);            // launch 2
    k_scan1<<<SCAN_BLOCKS, SCAN_CHUNK, 0, sA>>>();                      // launch 3

    // main branch: GEMM1 (DRAM/tensor-bound) — 4th launch, ncu slot
    k_gemm1_tc<<<(N_NODES + 127) / 128, 256, SM_SZ>>>(features);        // launch 4

    k_scan23<<<SCAN_BLOCKS, SCAN_CHUNK, 0, sA>>>();                     // launch 5
    k_fill<<<(N_EDGES + 255) / 256, 256, 0, sA>>>(edge_src, edge_dst, edge_w); // launch 6
    cudaEventRecord(eJoin, sA);
    cudaStreamWaitEvent(0, eJoin, 0);

    // joined tail
    k_agg1<<<(N_NODES + 7) / 8, 256>>>(b1);                             // launch 7
    k_gemm2<<<(N_NODES + 255) / 256, 256>>>(W2);                        // launch 8
    k_agg2_lsm<<<(N_NODES + 7) / 8, 256>>>(b2, out);                    // launch 9
}